// round 14
// baseline (speedup 1.0000x reference)
#include <cuda_runtime.h>
#include <cuda_fp16.h>
#include <cstdint>

// Problem constants
#define GB 64
#define GN 196
#define GD 768
#define GH 12
#define GHD 64
#define GSIDE 14
#define GM (GB*GN)   // 12544

// Scratch (device globals: allocation-free rule)
__device__ __align__(16) __half g_q_h[GB*GH*GN*GHD];     // fp16 Q/8 head-major
__device__ __align__(16) __half g_k_h[GB*GH*GN*GHD];     // fp16 K head-major
__device__ __align__(16) __half g_vt_h[GB*GH*GHD*GN];    // fp16 V transposed [head][64][196]
__device__ __align__(16) __half g_hs_h[(size_t)GM*GD];   // fp16 hidden states
__device__ __align__(16) __half g_wt_h[4*GD*GD];         // fp16 transposed weights [N][K]
__device__ __align__(16) __half g_ctx_h[(size_t)GM*GD];  // fp16 ctx

// ============================ helpers =======================================
__device__ __forceinline__ uint32_t smem_u32(const void* p) {
    uint32_t a;
    asm("{ .reg .u64 t; cvta.to.shared.u64 t, %1; cvt.u32.u64 %0, t; }" : "=r"(a) : "l"(p));
    return a;
}
__device__ __forceinline__ void cp16(uint32_t s, const void* g) {
    asm volatile("cp.async.cg.shared.global [%0], [%1], 16;" :: "r"(s), "l"(g));
}
__device__ __forceinline__ void cp_commit() { asm volatile("cp.async.commit_group;" ::: "memory"); }
__device__ __forceinline__ void cp_wait0()  { asm volatile("cp.async.wait_group 0;"  ::: "memory"); }
__device__ __forceinline__ void cp_wait1()  { asm volatile("cp.async.wait_group 1;"  ::: "memory"); }

__device__ __forceinline__ void mma_f16(float* c, const uint32_t* a, uint32_t b0, uint32_t b1) {
    asm volatile(
        "mma.sync.aligned.m16n8k16.row.col.f32.f16.f16.f32 "
        "{%0,%1,%2,%3}, {%4,%5,%6,%7}, {%8,%9}, {%0,%1,%2,%3};"
        : "+f"(c[0]), "+f"(c[1]), "+f"(c[2]), "+f"(c[3])
        : "r"(a[0]), "r"(a[1]), "r"(a[2]), "r"(a[3]), "r"(b0), "r"(b1));
}
__device__ __forceinline__ void ldsm_x4(uint32_t& r0, uint32_t& r1, uint32_t& r2,
                                        uint32_t& r3, uint32_t addr) {
    asm volatile("ldmatrix.sync.aligned.m8n8.x4.shared.b16 {%0,%1,%2,%3}, [%4];"
                 : "=r"(r0), "=r"(r1), "=r"(r2), "=r"(r3) : "r"(addr));
}
__device__ __forceinline__ uint32_t h2_bits(float x, float y) {
    __half2 h = __floats2half2_rn(x, y);
    return *(uint32_t*)&h;
}

// ===================== conversion pre-passes ================================
__global__ void conv_f2h(const float* __restrict__ s, __half* __restrict__ d, int n4) {
    int i = blockIdx.x * blockDim.x + threadIdx.x;
    if (i < n4) {
        float4 v = ((const float4*)s)[i];
        __half2 lo = __floats2half2_rn(v.x, v.y);
        __half2 hi = __floats2half2_rn(v.z, v.w);
        uint2 o;
        o.x = *(uint32_t*)&lo;
        o.y = *(uint32_t*)&hi;
        ((uint2*)d)[i] = o;
    }
}

// 4 transposes in one launch: z selects the matrix
__global__ void transpose_f2h4(const float* __restrict__ W0, const float* __restrict__ W1,
                               const float* __restrict__ W2, const float* __restrict__ W3,
                               __half* __restrict__ T)
{
    __shared__ float tile[32][33];
    const float* S = (blockIdx.z == 0) ? W0 : (blockIdx.z == 1) ? W1 :
                     (blockIdx.z == 2) ? W2 : W3;
    __half* D = T + (size_t)blockIdx.z * GD * GD;
    int tx = threadIdx.x, ty = threadIdx.y;
    int x = blockIdx.x * 32 + tx;
    int y = blockIdx.y * 32 + ty;
    #pragma unroll
    for (int j = 0; j < 32; j += 8)
        tile[ty + j][tx] = S[(size_t)(y + j) * GD + x];
    __syncthreads();
    int x2 = blockIdx.y * 32 + tx;
    int y2 = blockIdx.x * 32 + ty;
    #pragma unroll
    for (int j = 0; j < 32; j += 8)
        D[(size_t)(y2 + j) * GD + x2] = __float2half(tile[tx][ty + j]);
}

// ===================== fp16 mma.sync GEMM core ==============================
// ldmatrix fragment loads + 3-stage cp.async pipeline, ONE barrier per chunk.
#define BM 128
#define BN 128
#define HBK 64
#define HST 72
#define HASZ (BM*HST)
#define HBSZ (BN*HST)
#define NSTAGE 3
#define GEMM_SMEM (NSTAGE*(HASZ + HBSZ)*2)   // 110592 B
#define NCH (GD/HBK)                         // 12

struct GemmAcc { float a[2][8][4]; };

__device__ __forceinline__ void gemm_mainloop(
    const __half* __restrict__ Ag, const __half* __restrict__ Bg,
    __half* As, __half* Bs, GemmAcc& G)
{
    const uint32_t abase = smem_u32(As);
    const uint32_t bbase = smem_u32(Bs);
    const int tid = threadIdx.x;

    auto loadA = [&](int c, int buf) {
        const __half* ag = Ag + c*HBK;
        const uint32_t dst = abase + buf*HASZ*2;
        #pragma unroll
        for (int it = 0; it < 4; it++) {
            int idx = tid + 256*it;
            int m = idx >> 3, k8 = idx & 7;
            cp16(dst + (m*HST + k8*8)*2, ag + (size_t)m*GD + k8*8);
        }
    };
    auto loadB = [&](int c, int buf) {
        const __half* bg = Bg + c*HBK;
        const uint32_t dst = bbase + buf*HBSZ*2;
        #pragma unroll
        for (int it = 0; it < 4; it++) {
            int idx = tid + 256*it;
            int n = idx >> 3, k8 = idx & 7;
            cp16(dst + (n*HST + k8*8)*2, bg + (size_t)n*GD + k8*8);
        }
    };

    // prologue: stages 0 and 1 in flight
    loadA(0, 0); loadB(0, 0); cp_commit();
    loadA(1, 1); loadB(1, 1); cp_commit();

    const int wid = tid >> 5, lane = tid & 31;
    const int wm = wid & 3, wn = wid >> 2;

    const int a_lrow = (lane & 7) + ((lane >> 3) & 1) * 8;
    const int a_lk   = (lane >> 4) * 8;
    const uint32_t a_lane = abase + ((wm*32 + a_lrow)*HST + a_lk) * 2;
    const int b_ln  = (lane & 7) + (lane >> 4) * 8;
    const int b_lk  = ((lane >> 3) & 1) * 8;
    const uint32_t b_lane = bbase + ((wn*64 + b_ln)*HST + b_lk) * 2;

    #pragma unroll
    for (int i = 0; i < 2; i++)
        #pragma unroll
        for (int j = 0; j < 8; j++)
            #pragma unroll
            for (int k = 0; k < 4; k++) G.a[i][j][k] = 0.f;

    int buf = 0, lbuf = 2;
    for (int c = 0; c < NCH; c++) {
        // chunk c resident: with a successor group pending, wait<=1; tail waits 0
        if (c + 1 < NCH) cp_wait1(); else cp_wait0();
        __syncthreads();   // all warps past compute(c-1): buffer lbuf free to refill
        if (c + 2 < NCH) {
            loadA(c+2, lbuf);
            loadB(c+2, lbuf);
            cp_commit();
        }

        const uint32_t ab = a_lane + buf*(HASZ*2);
        const uint32_t bb = b_lane + buf*(HBSZ*2);

        #pragma unroll
        for (int s = 0; s < 4; s++) {
            uint32_t a[2][4], b[8][2];
            ldsm_x4(a[0][0], a[0][1], a[0][2], a[0][3], ab + s*32);
            ldsm_x4(a[1][0], a[1][1], a[1][2], a[1][3], ab + 16*HST*2 + s*32);
            #pragma unroll
            for (int nt2 = 0; nt2 < 4; nt2++)
                ldsm_x4(b[2*nt2][0], b[2*nt2][1], b[2*nt2+1][0], b[2*nt2+1][1],
                        bb + nt2*(16*HST*2) + s*32);
            #pragma unroll
            for (int mt = 0; mt < 2; mt++)
                #pragma unroll
                for (int nt = 0; nt < 8; nt++)
                    mma_f16(G.a[mt][nt], a[mt], b[nt][0], b[nt][1]);
        }

        buf  = (buf  == NSTAGE-1) ? 0 : buf + 1;
        lbuf = (lbuf == NSTAGE-1) ? 0 : lbuf + 1;
    }
}

// Fused QKV GEMM. Q written PRE-SCALED by 1/8; K head-major; V TRANSPOSED.
__global__ void __launch_bounds__(256, 2)
mma_gemm_qkv(const __half* __restrict__ A, const __half* __restrict__ BT,
             const float* __restrict__ bq, const float* __restrict__ bk,
             const float* __restrict__ bv,
             __half* __restrict__ Cq, __half* __restrict__ Ck, __half* __restrict__ Cvt)
{
    extern __shared__ __half smh[];
    const int bx = blockIdx.x, by = blockIdx.y;
    const int mat = bx / 6;                  // 0=Q 1=K 2=V
    const float* bias = (mat == 0) ? bq : (mat == 1) ? bk : bv;
    const int bxm = bx - mat*6;
    const float oscale = (mat == 0) ? 0.125f : 1.f;

    GemmAcc G;
    gemm_mainloop(A + (size_t)(by*BM)*GD, BT + (size_t)(bx*BN)*GD,
                  smh, smh + NSTAGE*HASZ, G);

    const int tid = threadIdx.x, wid = tid >> 5, lane = tid & 31;
    const int wm = wid & 3, wn = wid >> 2;
    const int lr = lane >> 2, lq = lane & 3;

    #pragma unroll
    for (int mt = 0; mt < 2; mt++) {
        #pragma unroll
        for (int h8 = 0; h8 < 2; h8++) {
            const int row = by*BM + wm*32 + mt*16 + h8*8 + lr;
            const int bb = row / GN, nn = row % GN;
            #pragma unroll
            for (int nt = 0; nt < 8; nt++) {
                const int col = bxm*BN + wn*64 + nt*8 + 2*lq;
                float vx = (G.a[mt][nt][h8*2+0] + bias[col]) * oscale;
                float vy = (G.a[mt][nt][h8*2+1] + bias[col+1]) * oscale;
                const int h = col >> 6, hd = col & 63;
                if (mat == 2) {
                    __half* vt = Cvt + (((size_t)bb*GH + h)*GHD)*GN;
                    vt[(size_t)hd*GN + nn]     = __float2half(vx);
                    vt[(size_t)(hd+1)*GN + nn] = __float2half(vy);
                } else {
                    __half* C = (mat == 0) ? Cq : Ck;
                    uint32_t bits = h2_bits(vx, vy);
                    *(uint32_t*)(C + (((size_t)bb*GH + h)*GN + nn)*GHD + hd) = bits;
                }
            }
        }
    }
}

// Output GEMM: fp32 output + bias
__global__ void __launch_bounds__(256, 2)
mma_gemm_out(const __half* __restrict__ A, const __half* __restrict__ BT,
             const float* __restrict__ bias, float* __restrict__ C)
{
    extern __shared__ __half smh[];
    const int bx = blockIdx.x, by = blockIdx.y;

    GemmAcc G;
    gemm_mainloop(A + (size_t)(by*BM)*GD, BT + (size_t)(bx*BN)*GD,
                  smh, smh + NSTAGE*HASZ, G);

    const int tid = threadIdx.x, wid = tid >> 5, lane = tid & 31;
    const int wm = wid & 3, wn = wid >> 2;
    const int lr = lane >> 2, lq = lane & 3;

    #pragma unroll
    for (int mt = 0; mt < 2; mt++) {
        #pragma unroll
        for (int h8 = 0; h8 < 2; h8++) {
            const int row = by*BM + wm*32 + mt*16 + h8*8 + lr;
            #pragma unroll
            for (int nt = 0; nt < 8; nt++) {
                const int col = bx*BN + wn*64 + nt*8 + 2*lq;
                float2 v;
                v.x = G.a[mt][nt][h8*2+0] + bias[col];
                v.y = G.a[mt][nt][h8*2+1] + bias[col+1];
                *(float2*)(C + (size_t)row*GD + col) = v;
            }
        }
    }
}

// ============ Flash-mma attention with ldmatrix fragment loads ==============
// (round-13 known-good)
#define AKST 72
#define AVST 216
#define ATT_SMEM (200*AKST*2 + 64*AVST*2 + 128*4)   // 57216 B

__global__ void __launch_bounds__(256, 3)
attn_flash(const __half* __restrict__ Qh, const __half* __restrict__ Kh,
           const __half* __restrict__ Vth, const float* __restrict__ Wsig,
           const float* __restrict__ bsigp, const float* __restrict__ tempp,
           __half* __restrict__ CTX)
{
    extern __shared__ __half smh[];
    __half* Ks = smh;                       // [200][72]
    __half* Vt = smh + 200*AKST;            // [64][216]
    float* invden = (float*)(smh + 200*AKST + 64*AVST);  // [128]

    const int bh = blockIdx.x >> 1, chunk = blockIdx.x & 1;
    const __half* Qg  = Qh  + (size_t)bh * GN * GHD;
    const __half* Kg  = Kh  + (size_t)bh * GN * GHD;
    const __half* Vtg = Vth + (size_t)bh * GHD * GN;

    const int tid = threadIdx.x;

    for (int idx = tid; idx < GN*32; idx += 256) {
        int j = idx >> 5, dp = idx & 31;
        *(uint32_t*)&Ks[j*AKST + 2*dp] = *(const uint32_t*)&Kg[j*GHD + 2*dp];
    }
    for (int idx = tid; idx < GHD*98; idx += 256) {
        int d = idx / 98, jp = idx - d*98;
        *(uint32_t*)&Vt[d*AVST + 2*jp] = *(const uint32_t*)&Vtg[d*GN + 2*jp];
    }
    for (int idx = tid; idx < GHD*10; idx += 256) {
        int d = idx / 10, c = idx - d*10;
        *(uint32_t*)&Vt[d*AVST + GN + 2*c] = 0u;
    }
    if (tid < 128) {
        int r = chunk*128 + tid;
        if (r > GN-1) r = GN-1;
        const __half* qr = Qg + r*GHD;
        float acc = 0.f;
        #pragma unroll 8
        for (int dp = 0; dp < 32; dp++) {
            float2 q = __half22float2(*(const __half2*)&qr[2*dp]);
            float2 w = *(const float2*)&Wsig[2*dp];
            acc += q.x*w.x + q.y*w.y;
        }
        float x = acc*8.f + bsigp[0];
        float sp = (x > 20.f) ? x : log1pf(expf(x));
        float sg = (sp + 1e-3f) * tempp[0];
        invden[tid] = -1.f / (2.f*sg*sg);
    }
    __syncthreads();

    const int w = tid >> 5, lane = tid & 31;
    const int m0 = chunk*128 + w*16;
    if (m0 >= GN) return;    // warp-uniform; no further CTA syncs

    const int lr = lane >> 2, lq = lane & 3;
    const int row_lo = m0 + lr, row_hi = row_lo + 8;
    const int rlo = (row_lo > GN-1) ? GN-1 : row_lo;
    const int rhi = (row_hi > GN-1) ? GN-1 : row_hi;
    const float ivd_lo = invden[w*16 + lr];
    const float ivd_hi = invden[w*16 + lr + 8];
    const int iy_lo = (rlo*2341) >> 15, ix_lo = rlo - GSIDE*iy_lo;
    const int iy_hi = (rhi*2341) >> 15, ix_hi = rhi - GSIDE*iy_hi;

    const int lm_row = ((lane >> 4) & 1) * 8 + (lane & 7);
    const int lm_kof = ((lane >> 3) & 1) * 8;
    const uint32_t k_lane = smem_u32(Ks) + (lm_row*AKST + lm_kof) * 2;
    const uint32_t v_lane = smem_u32(Vt) + (lm_row*AVST + lm_kof) * 2;

    uint32_t qa[4][4];
    {
        const __half* qlo = Qg + rlo*GHD + 2*lq;
        const __half* qhi = Qg + rhi*GHD + 2*lq;
        #pragma unroll
        for (int ks = 0; ks < 4; ks++) {
            qa[ks][0] = *(const uint32_t*)&qlo[16*ks];
            qa[ks][1] = *(const uint32_t*)&qhi[16*ks];
            qa[ks][2] = *(const uint32_t*)&qlo[16*ks + 8];
            qa[ks][3] = *(const uint32_t*)&qhi[16*ks + 8];
        }
    }

    float ctx[8][4];
    #pragma unroll
    for (int nt = 0; nt < 8; nt++)
        #pragma unroll
        for (int c = 0; c < 4; c++) ctx[nt][c] = 0.f;
    float l_lo = 0.f, l_hi = 0.f;

    #pragma unroll 1
    for (int pr = 0; pr < 13; pr++) {
        uint32_t kb[4][4];
        const uint32_t kpr = k_lane + (pr*16*AKST)*2;
        #pragma unroll
        for (int ks = 0; ks < 4; ks++)
            ldsm_x4(kb[ks][0], kb[ks][1], kb[ks][2], kb[ks][3], kpr + ks*32);

        float sa[4] = {0.f,0.f,0.f,0.f}, sb[4] = {0.f,0.f,0.f,0.f};
        #pragma unroll
        for (int ks = 0; ks < 4; ks++) {
            mma_f16(sa, qa[ks], kb[ks][0], kb[ks][1]);
            mma_f16(sb, qa[ks], kb[ks][2], kb[ks][3]);
        }

        const int j0 = pr*16 + 2*lq;
        float p[8];
        #pragma unroll
        for (int t = 0; t < 4; t++) {
            const int j = j0 + (t & 1) + ((t & 2) << 2);   // j0,j0+1,j0+8,j0+9
            const float s = (t & 2) ? sb[t & 1 ? 1 : 0] : sa[t & 1];
            const float s_hi = (t & 2) ? sb[(t & 1) + 2] : sa[(t & 1) + 2];
            if (j < GN) {
                const int jy = (j*2341) >> 15, jx = j - GSIDE*jy;
                const int dyl = iy_lo - jy, dxl = ix_lo - jx;
                const int dyh = iy_hi - jy, dxh = ix_hi - jx;
                const float mlo = __expf((float)(dyl*dyl + dxl*dxl) * ivd_lo);
                const float mhi = __expf((float)(dyh*dyh + dxh*dxh) * ivd_hi);
                p[t*2]   = __expf(mlo * s);
                p[t*2+1] = __expf(mhi * s_hi);
            } else {
                p[t*2] = 0.f;
                p[t*2+1] = 0.f;
            }
        }
        l_lo += (p[0] + p[2]) + (p[4] + p[6]);
        l_hi += (p[1] + p[3]) + (p[5] + p[7]);

        uint32_t pa[4];
        pa[0] = h2_bits(p[0], p[2]);
        pa[1] = h2_bits(p[1], p[3]);
        pa[2] = h2_bits(p[4], p[6]);
        pa[3] = h2_bits(p[5], p[7]);

        const uint32_t vpr = v_lane + (pr*16)*2;
        #pragma unroll
        for (int dg = 0; dg < 4; dg++) {
            uint32_t vb0, vb1, vb2, vb3;
            ldsm_x4(vb0, vb1, vb2, vb3, vpr + dg*(16*AVST)*2);
            mma_f16(ctx[2*dg],     pa, vb0, vb1);
            mma_f16(ctx[2*dg + 1], pa, vb2, vb3);
        }
    }

    l_lo += __shfl_xor_sync(0xffffffffu, l_lo, 1);
    l_lo += __shfl_xor_sync(0xffffffffu, l_lo, 2);
    l_hi += __shfl_xor_sync(0xffffffffu, l_hi, 1);
    l_hi += __shfl_xor_sync(0xffffffffu, l_hi, 2);
    const float il_lo = 1.f / l_lo, il_hi = 1.f / l_hi;

    const int b = bh / GH, h = bh % GH;
    __half* out_lo = CTX + ((size_t)(b*GN + row_lo))*GD + h*GHD + 2*lq;
    __half* out_hi = CTX + ((size_t)(b*GN + row_hi))*GD + h*GHD + 2*lq;
    #pragma unroll
    for (int nt = 0; nt < 8; nt++) {
        if (row_lo < GN)
            *(uint32_t*)&out_lo[nt*8] = h2_bits(ctx[nt][0]*il_lo, ctx[nt][1]*il_lo);
        if (row_hi < GN)
            *(uint32_t*)&out_hi[nt*8] = h2_bits(ctx[nt][2]*il_hi, ctx[nt][3]*il_hi);
    }
}

// ---------------- launch ----------------------------------------------------
extern "C" void kernel_launch(void* const* d_in, const int* in_sizes, int n_in,
                              void* d_out, int out_size)
{
    const float* hs   = (const float*)d_in[0];
    const float* temp = (const float*)d_in[1];
    const float* Wq   = (const float*)d_in[2];
    const float* bq   = (const float*)d_in[3];
    const float* Wk   = (const float*)d_in[4];
    const float* bk   = (const float*)d_in[5];
    const float* Wv   = (const float*)d_in[6];
    const float* bv   = (const float*)d_in[7];
    const float* Wo   = (const float*)d_in[8];
    const float* bo   = (const float*)d_in[9];
    const float* Wsig = (const float*)d_in[10];
    const float* bsig = (const float*)d_in[11];
    float* out = (float*)d_out;

    __half *gq, *gk, *gvt, *ghs, *gwt, *gctx;
    cudaGetSymbolAddress((void**)&gq,   g_q_h);
    cudaGetSymbolAddress((void**)&gk,   g_k_h);
    cudaGetSymbolAddress((void**)&gvt,  g_vt_h);
    cudaGetSymbolAddress((void**)&ghs,  g_hs_h);
    cudaGetSymbolAddress((void**)&gwt,  g_wt_h);
    cudaGetSymbolAddress((void**)&gctx, g_ctx_h);

    cudaFuncSetAttribute(attn_flash,
                         cudaFuncAttributeMaxDynamicSharedMemorySize, ATT_SMEM);
    cudaFuncSetAttribute(mma_gemm_qkv,
                         cudaFuncAttributeMaxDynamicSharedMemorySize, GEMM_SMEM);
    cudaFuncSetAttribute(mma_gemm_out,
                         cudaFuncAttributeMaxDynamicSharedMemorySize, GEMM_SMEM);

    __half* wto = gwt + 3ull*GD*GD;

    const int nhs4 = GM*GD/4;
    conv_f2h<<<(nhs4 + 255)/256, 256>>>(hs, ghs, nhs4);
    dim3 tb(32, 8), tg(GD/32, GD/32, 4);
    transpose_f2h4<<<tg, tb>>>(Wq, Wk, Wv, Wo, gwt);

    dim3 gqkv(3*GD/BN, GM/BM);   // (18, 98)
    mma_gemm_qkv<<<gqkv, 256, GEMM_SMEM>>>(ghs, gwt, bq, bk, bv, gq, gk, gvt);
    attn_flash<<<GB*GH*2, 256, ATT_SMEM>>>(gq, gk, gvt, Wsig, bsig, temp, gctx);
    dim3 gout(GD/BN, GM/BM);     // (6, 98)
    mma_gemm_out<<<gout, 256, GEMM_SMEM>>>(gctx, wto, bo, out);
}

// round 15
// speedup vs baseline: 1.0087x; 1.0087x over previous
#include <cuda_runtime.h>
#include <cuda_fp16.h>
#include <cstdint>

// Problem constants
#define GB 64
#define GN 196
#define GD 768
#define GH 12
#define GHD 64
#define GSIDE 14
#define GM (GB*GN)   // 12544

// Scratch (device globals: allocation-free rule)
__device__ __align__(16) __half g_q_h[GB*GH*GN*GHD];     // fp16 Q/8 head-major
__device__ __align__(16) __half g_k_h[GB*GH*GN*GHD];     // fp16 K head-major
__device__ __align__(16) __half g_vt_h[GB*GH*GHD*GN];    // fp16 V transposed [head][64][196]
__device__ __align__(16) __half g_hs_h[(size_t)GM*GD];   // fp16 hidden states
__device__ __align__(16) __half g_wt_h[4*GD*GD];         // fp16 transposed weights [N][K]
__device__ __align__(16) __half g_ctx_h[(size_t)GM*GD];  // fp16 ctx

// ============================ helpers =======================================
__device__ __forceinline__ uint32_t smem_u32(const void* p) {
    uint32_t a;
    asm("{ .reg .u64 t; cvta.to.shared.u64 t, %1; cvt.u32.u64 %0, t; }" : "=r"(a) : "l"(p));
    return a;
}
__device__ __forceinline__ void cp16(uint32_t s, const void* g) {
    asm volatile("cp.async.cg.shared.global [%0], [%1], 16;" :: "r"(s), "l"(g));
}
__device__ __forceinline__ void cp_commit() { asm volatile("cp.async.commit_group;" ::: "memory"); }
__device__ __forceinline__ void cp_wait0()  { asm volatile("cp.async.wait_group 0;"  ::: "memory"); }
__device__ __forceinline__ void cp_wait1()  { asm volatile("cp.async.wait_group 1;"  ::: "memory"); }

__device__ __forceinline__ void mma_f16(float* c, const uint32_t* a, uint32_t b0, uint32_t b1) {
    asm volatile(
        "mma.sync.aligned.m16n8k16.row.col.f32.f16.f16.f32 "
        "{%0,%1,%2,%3}, {%4,%5,%6,%7}, {%8,%9}, {%0,%1,%2,%3};"
        : "+f"(c[0]), "+f"(c[1]), "+f"(c[2]), "+f"(c[3])
        : "r"(a[0]), "r"(a[1]), "r"(a[2]), "r"(a[3]), "r"(b0), "r"(b1));
}
__device__ __forceinline__ void ldsm_x4(uint32_t& r0, uint32_t& r1, uint32_t& r2,
                                        uint32_t& r3, uint32_t addr) {
    asm volatile("ldmatrix.sync.aligned.m8n8.x4.shared.b16 {%0,%1,%2,%3}, [%4];"
                 : "=r"(r0), "=r"(r1), "=r"(r2), "=r"(r3) : "r"(addr));
}
__device__ __forceinline__ uint32_t h2_bits(float x, float y) {
    __half2 h = __floats2half2_rn(x, y);
    return *(uint32_t*)&h;
}

// ===================== conversion pre-passes ================================
__global__ void conv_f2h(const float* __restrict__ s, __half* __restrict__ d, int n4) {
    int i = blockIdx.x * blockDim.x + threadIdx.x;
    if (i < n4) {
        float4 v = ((const float4*)s)[i];
        __half2 lo = __floats2half2_rn(v.x, v.y);
        __half2 hi = __floats2half2_rn(v.z, v.w);
        uint2 o;
        o.x = *(uint32_t*)&lo;
        o.y = *(uint32_t*)&hi;
        ((uint2*)d)[i] = o;
    }
}

// 4 transposes in one launch: z selects the matrix
__global__ void transpose_f2h4(const float* __restrict__ W0, const float* __restrict__ W1,
                               const float* __restrict__ W2, const float* __restrict__ W3,
                               __half* __restrict__ T)
{
    __shared__ float tile[32][33];
    const float* S = (blockIdx.z == 0) ? W0 : (blockIdx.z == 1) ? W1 :
                     (blockIdx.z == 2) ? W2 : W3;
    __half* D = T + (size_t)blockIdx.z * GD * GD;
    int tx = threadIdx.x, ty = threadIdx.y;
    int x = blockIdx.x * 32 + tx;
    int y = blockIdx.y * 32 + ty;
    #pragma unroll
    for (int j = 0; j < 32; j += 8)
        tile[ty + j][tx] = S[(size_t)(y + j) * GD + x];
    __syncthreads();
    int x2 = blockIdx.y * 32 + tx;
    int y2 = blockIdx.x * 32 + ty;
    #pragma unroll
    for (int j = 0; j < 32; j += 8)
        D[(size_t)(y2 + j) * GD + x2] = __float2half(tile[tx][ty + j]);
}

// ===================== fp16 mma.sync GEMM core ==============================
// 512 threads / 16 warps (4m x 4n), warp tile 32x32. ldmatrix + 3-stage
// cp.async pipeline, one barrier per chunk. ~60 regs -> 2 CTAs = 32 warps/SM.
#define BM 128
#define BN 128
#define HBK 64
#define HST 72
#define HASZ (BM*HST)
#define HBSZ (BN*HST)
#define NSTAGE 3
#define GEMM_SMEM (NSTAGE*(HASZ + HBSZ)*2)   // 110592 B
#define NCH (GD/HBK)                         // 12
#define GTHR 512

struct GemmAcc { float a[2][4][4]; };   // [mt][nt][c]

__device__ __forceinline__ void gemm_mainloop(
    const __half* __restrict__ Ag, const __half* __restrict__ Bg,
    __half* As, __half* Bs, GemmAcc& G)
{
    const uint32_t abase = smem_u32(As);
    const uint32_t bbase = smem_u32(Bs);
    const int tid = threadIdx.x;

    auto loadA = [&](int c, int buf) {
        const __half* ag = Ag + c*HBK;
        const uint32_t dst = abase + buf*HASZ*2;
        #pragma unroll
        for (int it = 0; it < 2; it++) {
            int idx = tid + GTHR*it;
            int m = idx >> 3, k8 = idx & 7;
            cp16(dst + (m*HST + k8*8)*2, ag + (size_t)m*GD + k8*8);
        }
    };
    auto loadB = [&](int c, int buf) {
        const __half* bg = Bg + c*HBK;
        const uint32_t dst = bbase + buf*HBSZ*2;
        #pragma unroll
        for (int it = 0; it < 2; it++) {
            int idx = tid + GTHR*it;
            int n = idx >> 3, k8 = idx & 7;
            cp16(dst + (n*HST + k8*8)*2, bg + (size_t)n*GD + k8*8);
        }
    };

    // prologue: stages 0 and 1 in flight
    loadA(0, 0); loadB(0, 0); cp_commit();
    loadA(1, 1); loadB(1, 1); cp_commit();

    const int wid = tid >> 5, lane = tid & 31;
    const int wm = wid & 3, wn = wid >> 2;   // 4 x 4 warp grid

    const int a_lrow = (lane & 7) + ((lane >> 3) & 1) * 8;
    const int a_lk   = (lane >> 4) * 8;
    const uint32_t a_lane = abase + ((wm*32 + a_lrow)*HST + a_lk) * 2;
    const int b_ln  = (lane & 7) + (lane >> 4) * 8;
    const int b_lk  = ((lane >> 3) & 1) * 8;
    const uint32_t b_lane = bbase + ((wn*32 + b_ln)*HST + b_lk) * 2;

    #pragma unroll
    for (int i = 0; i < 2; i++)
        #pragma unroll
        for (int j = 0; j < 4; j++)
            #pragma unroll
            for (int k = 0; k < 4; k++) G.a[i][j][k] = 0.f;

    int buf = 0, lbuf = 2;
    for (int c = 0; c < NCH; c++) {
        if (c + 1 < NCH) cp_wait1(); else cp_wait0();
        __syncthreads();
        if (c + 2 < NCH) {
            loadA(c+2, lbuf);
            loadB(c+2, lbuf);
            cp_commit();
        }

        const uint32_t ab = a_lane + buf*(HASZ*2);
        const uint32_t bb = b_lane + buf*(HBSZ*2);

        #pragma unroll
        for (int s = 0; s < 4; s++) {
            uint32_t a[2][4], b[4][2];
            ldsm_x4(a[0][0], a[0][1], a[0][2], a[0][3], ab + s*32);
            ldsm_x4(a[1][0], a[1][1], a[1][2], a[1][3], ab + 16*HST*2 + s*32);
            ldsm_x4(b[0][0], b[0][1], b[1][0], b[1][1], bb + s*32);
            ldsm_x4(b[2][0], b[2][1], b[3][0], b[3][1], bb + 16*HST*2 + s*32);
            #pragma unroll
            for (int mt = 0; mt < 2; mt++)
                #pragma unroll
                for (int nt = 0; nt < 4; nt++)
                    mma_f16(G.a[mt][nt], a[mt], b[nt][0], b[nt][1]);
        }

        buf  = (buf  == NSTAGE-1) ? 0 : buf + 1;
        lbuf = (lbuf == NSTAGE-1) ? 0 : lbuf + 1;
    }
}

// Fused QKV GEMM. Q written PRE-SCALED by 1/8; K head-major; V TRANSPOSED.
__global__ void __launch_bounds__(GTHR, 2)
mma_gemm_qkv(const __half* __restrict__ A, const __half* __restrict__ BT,
             const float* __restrict__ bq, const float* __restrict__ bk,
             const float* __restrict__ bv,
             __half* __restrict__ Cq, __half* __restrict__ Ck, __half* __restrict__ Cvt)
{
    extern __shared__ __half smh[];
    const int bx = blockIdx.x, by = blockIdx.y;
    const int mat = bx / 6;                  // 0=Q 1=K 2=V
    const float* bias = (mat == 0) ? bq : (mat == 1) ? bk : bv;
    const int bxm = bx - mat*6;
    const float oscale = (mat == 0) ? 0.125f : 1.f;

    GemmAcc G;
    gemm_mainloop(A + (size_t)(by*BM)*GD, BT + (size_t)(bx*BN)*GD,
                  smh, smh + NSTAGE*HASZ, G);

    const int tid = threadIdx.x, wid = tid >> 5, lane = tid & 31;
    const int wm = wid & 3, wn = wid >> 2;
    const int lr = lane >> 2, lq = lane & 3;

    #pragma unroll
    for (int mt = 0; mt < 2; mt++) {
        #pragma unroll
        for (int h8 = 0; h8 < 2; h8++) {
            const int row = by*BM + wm*32 + mt*16 + h8*8 + lr;
            const int bb = row / GN, nn = row % GN;
            #pragma unroll
            for (int nt = 0; nt < 4; nt++) {
                const int col = bxm*BN + wn*32 + nt*8 + 2*lq;
                float vx = (G.a[mt][nt][h8*2+0] + bias[col]) * oscale;
                float vy = (G.a[mt][nt][h8*2+1] + bias[col+1]) * oscale;
                const int h = col >> 6, hd = col & 63;
                if (mat == 2) {
                    __half* vt = Cvt + (((size_t)bb*GH + h)*GHD)*GN;
                    vt[(size_t)hd*GN + nn]     = __float2half(vx);
                    vt[(size_t)(hd+1)*GN + nn] = __float2half(vy);
                } else {
                    __half* C = (mat == 0) ? Cq : Ck;
                    uint32_t bits = h2_bits(vx, vy);
                    *(uint32_t*)(C + (((size_t)bb*GH + h)*GN + nn)*GHD + hd) = bits;
                }
            }
        }
    }
}

// Output GEMM: fp32 output + bias
__global__ void __launch_bounds__(GTHR, 2)
mma_gemm_out(const __half* __restrict__ A, const __half* __restrict__ BT,
             const float* __restrict__ bias, float* __restrict__ C)
{
    extern __shared__ __half smh[];
    const int bx = blockIdx.x, by = blockIdx.y;

    GemmAcc G;
    gemm_mainloop(A + (size_t)(by*BM)*GD, BT + (size_t)(bx*BN)*GD,
                  smh, smh + NSTAGE*HASZ, G);

    const int tid = threadIdx.x, wid = tid >> 5, lane = tid & 31;
    const int wm = wid & 3, wn = wid >> 2;
    const int lr = lane >> 2, lq = lane & 3;

    #pragma unroll
    for (int mt = 0; mt < 2; mt++) {
        #pragma unroll
        for (int h8 = 0; h8 < 2; h8++) {
            const int row = by*BM + wm*32 + mt*16 + h8*8 + lr;
            #pragma unroll
            for (int nt = 0; nt < 4; nt++) {
                const int col = bx*BN + wn*32 + nt*8 + 2*lq;
                float2 v;
                v.x = G.a[mt][nt][h8*2+0] + bias[col];
                v.y = G.a[mt][nt][h8*2+1] + bias[col+1];
                *(float2*)(C + (size_t)row*GD + col) = v;
            }
        }
    }
}

// ============ Flash-mma attention with ldmatrix fragment loads ==============
// (round-13 known-good)
#define AKST 72
#define AVST 216
#define ATT_SMEM (200*AKST*2 + 64*AVST*2 + 128*4)   // 57216 B

__global__ void __launch_bounds__(256, 3)
attn_flash(const __half* __restrict__ Qh, const __half* __restrict__ Kh,
           const __half* __restrict__ Vth, const float* __restrict__ Wsig,
           const float* __restrict__ bsigp, const float* __restrict__ tempp,
           __half* __restrict__ CTX)
{
    extern __shared__ __half smh[];
    __half* Ks = smh;                       // [200][72]
    __half* Vt = smh + 200*AKST;            // [64][216]
    float* invden = (float*)(smh + 200*AKST + 64*AVST);  // [128]

    const int bh = blockIdx.x >> 1, chunk = blockIdx.x & 1;
    const __half* Qg  = Qh  + (size_t)bh * GN * GHD;
    const __half* Kg  = Kh  + (size_t)bh * GN * GHD;
    const __half* Vtg = Vth + (size_t)bh * GHD * GN;

    const int tid = threadIdx.x;

    for (int idx = tid; idx < GN*32; idx += 256) {
        int j = idx >> 5, dp = idx & 31;
        *(uint32_t*)&Ks[j*AKST + 2*dp] = *(const uint32_t*)&Kg[j*GHD + 2*dp];
    }
    for (int idx = tid; idx < GHD*98; idx += 256) {
        int d = idx / 98, jp = idx - d*98;
        *(uint32_t*)&Vt[d*AVST + 2*jp] = *(const uint32_t*)&Vtg[d*GN + 2*jp];
    }
    for (int idx = tid; idx < GHD*10; idx += 256) {
        int d = idx / 10, c = idx - d*10;
        *(uint32_t*)&Vt[d*AVST + GN + 2*c] = 0u;
    }
    if (tid < 128) {
        int r = chunk*128 + tid;
        if (r > GN-1) r = GN-1;
        const __half* qr = Qg + r*GHD;
        float acc = 0.f;
        #pragma unroll 8
        for (int dp = 0; dp < 32; dp++) {
            float2 q = __half22float2(*(const __half2*)&qr[2*dp]);
            float2 w = *(const float2*)&Wsig[2*dp];
            acc += q.x*w.x + q.y*w.y;
        }
        float x = acc*8.f + bsigp[0];
        float sp = (x > 20.f) ? x : log1pf(expf(x));
        float sg = (sp + 1e-3f) * tempp[0];
        invden[tid] = -1.f / (2.f*sg*sg);
    }
    __syncthreads();

    const int w = tid >> 5, lane = tid & 31;
    const int m0 = chunk*128 + w*16;
    if (m0 >= GN) return;    // warp-uniform; no further CTA syncs

    const int lr = lane >> 2, lq = lane & 3;
    const int row_lo = m0 + lr, row_hi = row_lo + 8;
    const int rlo = (row_lo > GN-1) ? GN-1 : row_lo;
    const int rhi = (row_hi > GN-1) ? GN-1 : row_hi;
    const float ivd_lo = invden[w*16 + lr];
    const float ivd_hi = invden[w*16 + lr + 8];
    const int iy_lo = (rlo*2341) >> 15, ix_lo = rlo - GSIDE*iy_lo;
    const int iy_hi = (rhi*2341) >> 15, ix_hi = rhi - GSIDE*iy_hi;

    const int lm_row = ((lane >> 4) & 1) * 8 + (lane & 7);
    const int lm_kof = ((lane >> 3) & 1) * 8;
    const uint32_t k_lane = smem_u32(Ks) + (lm_row*AKST + lm_kof) * 2;
    const uint32_t v_lane = smem_u32(Vt) + (lm_row*AVST + lm_kof) * 2;

    uint32_t qa[4][4];
    {
        const __half* qlo = Qg + rlo*GHD + 2*lq;
        const __half* qhi = Qg + rhi*GHD + 2*lq;
        #pragma unroll
        for (int ks = 0; ks < 4; ks++) {
            qa[ks][0] = *(const uint32_t*)&qlo[16*ks];
            qa[ks][1] = *(const uint32_t*)&qhi[16*ks];
            qa[ks][2] = *(const uint32_t*)&qlo[16*ks + 8];
            qa[ks][3] = *(const uint32_t*)&qhi[16*ks + 8];
        }
    }

    float ctx[8][4];
    #pragma unroll
    for (int nt = 0; nt < 8; nt++)
        #pragma unroll
        for (int c = 0; c < 4; c++) ctx[nt][c] = 0.f;
    float l_lo = 0.f, l_hi = 0.f;

    #pragma unroll 1
    for (int pr = 0; pr < 13; pr++) {
        uint32_t kb[4][4];
        const uint32_t kpr = k_lane + (pr*16*AKST)*2;
        #pragma unroll
        for (int ks = 0; ks < 4; ks++)
            ldsm_x4(kb[ks][0], kb[ks][1], kb[ks][2], kb[ks][3], kpr + ks*32);

        float sa[4] = {0.f,0.f,0.f,0.f}, sb[4] = {0.f,0.f,0.f,0.f};
        #pragma unroll
        for (int ks = 0; ks < 4; ks++) {
            mma_f16(sa, qa[ks], kb[ks][0], kb[ks][1]);
            mma_f16(sb, qa[ks], kb[ks][2], kb[ks][3]);
        }

        const int j0 = pr*16 + 2*lq;
        float p[8];
        #pragma unroll
        for (int t = 0; t < 4; t++) {
            const int j = j0 + (t & 1) + ((t & 2) << 2);   // j0,j0+1,j0+8,j0+9
            const float s = (t & 2) ? sb[t & 1 ? 1 : 0] : sa[t & 1];
            const float s_hi = (t & 2) ? sb[(t & 1) + 2] : sa[(t & 1) + 2];
            if (j < GN) {
                const int jy = (j*2341) >> 15, jx = j - GSIDE*jy;
                const int dyl = iy_lo - jy, dxl = ix_lo - jx;
                const int dyh = iy_hi - jy, dxh = ix_hi - jx;
                const float mlo = __expf((float)(dyl*dyl + dxl*dxl) * ivd_lo);
                const float mhi = __expf((float)(dyh*dyh + dxh*dxh) * ivd_hi);
                p[t*2]   = __expf(mlo * s);
                p[t*2+1] = __expf(mhi * s_hi);
            } else {
                p[t*2] = 0.f;
                p[t*2+1] = 0.f;
            }
        }
        l_lo += (p[0] + p[2]) + (p[4] + p[6]);
        l_hi += (p[1] + p[3]) + (p[5] + p[7]);

        uint32_t pa[4];
        pa[0] = h2_bits(p[0], p[2]);
        pa[1] = h2_bits(p[1], p[3]);
        pa[2] = h2_bits(p[4], p[6]);
        pa[3] = h2_bits(p[5], p[7]);

        const uint32_t vpr = v_lane + (pr*16)*2;
        #pragma unroll
        for (int dg = 0; dg < 4; dg++) {
            uint32_t vb0, vb1, vb2, vb3;
            ldsm_x4(vb0, vb1, vb2, vb3, vpr + dg*(16*AVST)*2);
            mma_f16(ctx[2*dg],     pa, vb0, vb1);
            mma_f16(ctx[2*dg + 1], pa, vb2, vb3);
        }
    }

    l_lo += __shfl_xor_sync(0xffffffffu, l_lo, 1);
    l_lo += __shfl_xor_sync(0xffffffffu, l_lo, 2);
    l_hi += __shfl_xor_sync(0xffffffffu, l_hi, 1);
    l_hi += __shfl_xor_sync(0xffffffffu, l_hi, 2);
    const float il_lo = 1.f / l_lo, il_hi = 1.f / l_hi;

    const int b = bh / GH, h = bh % GH;
    __half* out_lo = CTX + ((size_t)(b*GN + row_lo))*GD + h*GHD + 2*lq;
    __half* out_hi = CTX + ((size_t)(b*GN + row_hi))*GD + h*GHD + 2*lq;
    #pragma unroll
    for (int nt = 0; nt < 8; nt++) {
        if (row_lo < GN)
            *(uint32_t*)&out_lo[nt*8] = h2_bits(ctx[nt][0]*il_lo, ctx[nt][1]*il_lo);
        if (row_hi < GN)
            *(uint32_t*)&out_hi[nt*8] = h2_bits(ctx[nt][2]*il_hi, ctx[nt][3]*il_hi);
    }
}

// ---------------- launch ----------------------------------------------------
extern "C" void kernel_launch(void* const* d_in, const int* in_sizes, int n_in,
                              void* d_out, int out_size)
{
    const float* hs   = (const float*)d_in[0];
    const float* temp = (const float*)d_in[1];
    const float* Wq   = (const float*)d_in[2];
    const float* bq   = (const float*)d_in[3];
    const float* Wk   = (const float*)d_in[4];
    const float* bk   = (const float*)d_in[5];
    const float* Wv   = (const float*)d_in[6];
    const float* bv   = (const float*)d_in[7];
    const float* Wo   = (const float*)d_in[8];
    const float* bo   = (const float*)d_in[9];
    const float* Wsig = (const float*)d_in[10];
    const float* bsig = (const float*)d_in[11];
    float* out = (float*)d_out;

    __half *gq, *gk, *gvt, *ghs, *gwt, *gctx;
    cudaGetSymbolAddress((void**)&gq,   g_q_h);
    cudaGetSymbolAddress((void**)&gk,   g_k_h);
    cudaGetSymbolAddress((void**)&gvt,  g_vt_h);
    cudaGetSymbolAddress((void**)&ghs,  g_hs_h);
    cudaGetSymbolAddress((void**)&gwt,  g_wt_h);
    cudaGetSymbolAddress((void**)&gctx, g_ctx_h);

    cudaFuncSetAttribute(attn_flash,
                         cudaFuncAttributeMaxDynamicSharedMemorySize, ATT_SMEM);
    cudaFuncSetAttribute(mma_gemm_qkv,
                         cudaFuncAttributeMaxDynamicSharedMemorySize, GEMM_SMEM);
    cudaFuncSetAttribute(mma_gemm_out,
                         cudaFuncAttributeMaxDynamicSharedMemorySize, GEMM_SMEM);

    __half* wto = gwt + 3ull*GD*GD;

    const int nhs4 = GM*GD/4;
    conv_f2h<<<(nhs4 + 255)/256, 256>>>(hs, ghs, nhs4);
    dim3 tb(32, 8), tg(GD/32, GD/32, 4);
    transpose_f2h4<<<tg, tb>>>(Wq, Wk, Wv, Wo, gwt);

    dim3 gqkv(3*GD/BN, GM/BM);   // (18, 98)
    mma_gemm_qkv<<<gqkv, GTHR, GEMM_SMEM>>>(ghs, gwt, bq, bk, bv, gq, gk, gvt);
    attn_flash<<<GB*GH*2, 256, ATT_SMEM>>>(gq, gk, gvt, Wsig, bsig, temp, gctx);
    dim3 gout(GD/BN, GM/BM);     // (6, 98)
    mma_gemm_out<<<gout, GTHR, GEMM_SMEM>>>(gctx, wto, bo, out);
}

// round 16
// speedup vs baseline: 1.0850x; 1.0756x over previous
#include <cuda_runtime.h>
#include <cuda_fp16.h>
#include <cstdint>

// Problem constants
#define GB 64
#define GN 196
#define GD 768
#define GH 12
#define GHD 64
#define GSIDE 14
#define GM (GB*GN)   // 12544

// Scratch (device globals: allocation-free rule)
__device__ __align__(16) __half g_q_h[GB*GH*GN*GHD];     // fp16 Q/8 head-major
__device__ __align__(16) __half g_k_h[GB*GH*GN*GHD];     // fp16 K head-major
__device__ __align__(16) __half g_vt_h[GB*GH*GHD*GN];    // fp16 V transposed [head][64][196]
__device__ __align__(16) __half g_hs_h[(size_t)GM*GD];   // fp16 hidden states
__device__ __align__(16) __half g_wt_h[4*GD*GD];         // fp16 transposed weights [N][K]
__device__ __align__(16) __half g_ctx_h[(size_t)GM*GD];  // fp16 ctx

// ============================ helpers =======================================
__device__ __forceinline__ uint32_t smem_u32(const void* p) {
    uint32_t a;
    asm("{ .reg .u64 t; cvta.to.shared.u64 t, %1; cvt.u32.u64 %0, t; }" : "=r"(a) : "l"(p));
    return a;
}
__device__ __forceinline__ void cp16(uint32_t s, const void* g) {
    asm volatile("cp.async.cg.shared.global [%0], [%1], 16;" :: "r"(s), "l"(g));
}
__device__ __forceinline__ void cp_commit() { asm volatile("cp.async.commit_group;" ::: "memory"); }
__device__ __forceinline__ void cp_wait0()  { asm volatile("cp.async.wait_group 0;"  ::: "memory"); }
__device__ __forceinline__ void cp_wait1()  { asm volatile("cp.async.wait_group 1;"  ::: "memory"); }

__device__ __forceinline__ void mma_f16(float* c, const uint32_t* a, uint32_t b0, uint32_t b1) {
    asm volatile(
        "mma.sync.aligned.m16n8k16.row.col.f32.f16.f16.f32 "
        "{%0,%1,%2,%3}, {%4,%5,%6,%7}, {%8,%9}, {%0,%1,%2,%3};"
        : "+f"(c[0]), "+f"(c[1]), "+f"(c[2]), "+f"(c[3])
        : "r"(a[0]), "r"(a[1]), "r"(a[2]), "r"(a[3]), "r"(b0), "r"(b1));
}
__device__ __forceinline__ void ldsm_x4(uint32_t& r0, uint32_t& r1, uint32_t& r2,
                                        uint32_t& r3, uint32_t addr) {
    asm volatile("ldmatrix.sync.aligned.m8n8.x4.shared.b16 {%0,%1,%2,%3}, [%4];"
                 : "=r"(r0), "=r"(r1), "=r"(r2), "=r"(r3) : "r"(addr));
}
__device__ __forceinline__ uint32_t h2_bits(float x, float y) {
    __half2 h = __floats2half2_rn(x, y);
    return *(uint32_t*)&h;
}

// ===================== conversion pre-passes ================================
__global__ void conv_f2h(const float* __restrict__ s, __half* __restrict__ d, int n4) {
    int i = blockIdx.x * blockDim.x + threadIdx.x;
    if (i < n4) {
        float4 v = ((const float4*)s)[i];
        __half2 lo = __floats2half2_rn(v.x, v.y);
        __half2 hi = __floats2half2_rn(v.z, v.w);
        uint2 o;
        o.x = *(uint32_t*)&lo;
        o.y = *(uint32_t*)&hi;
        ((uint2*)d)[i] = o;
    }
}

// 4 transposes in one launch: z selects the matrix
__global__ void transpose_f2h4(const float* __restrict__ W0, const float* __restrict__ W1,
                               const float* __restrict__ W2, const float* __restrict__ W3,
                               __half* __restrict__ T)
{
    __shared__ float tile[32][33];
    const float* S = (blockIdx.z == 0) ? W0 : (blockIdx.z == 1) ? W1 :
                     (blockIdx.z == 2) ? W2 : W3;
    __half* D = T + (size_t)blockIdx.z * GD * GD;
    int tx = threadIdx.x, ty = threadIdx.y;
    int x = blockIdx.x * 32 + tx;
    int y = blockIdx.y * 32 + ty;
    #pragma unroll
    for (int j = 0; j < 32; j += 8)
        tile[ty + j][tx] = S[(size_t)(y + j) * GD + x];
    __syncthreads();
    int x2 = blockIdx.y * 32 + tx;
    int y2 = blockIdx.x * 32 + ty;
    #pragma unroll
    for (int j = 0; j < 32; j += 8)
        D[(size_t)(y2 + j) * GD + x2] = __float2half(tile[tx][ty + j]);
}

// ===================== fp16 mma.sync GEMM core ==============================
// 512 threads / 16 warps (4m x 4n), warp tile 32x32. ldmatrix + 3-stage
// cp.async pipeline, one barrier per chunk.
#define BM 128
#define BN 128
#define HBK 64
#define HST 72
#define HASZ (BM*HST)
#define HBSZ (BN*HST)
#define NSTAGE 3
#define GEMM_SMEM (NSTAGE*(HASZ + HBSZ)*2)   // 110592 B
#define NCH (GD/HBK)                         // 12
#define GTHR 512

struct GemmAcc { float a[2][4][4]; };   // [mt][nt][c]

__device__ __forceinline__ void gemm_mainloop(
    const __half* __restrict__ Ag, const __half* __restrict__ Bg,
    __half* As, __half* Bs, GemmAcc& G)
{
    const uint32_t abase = smem_u32(As);
    const uint32_t bbase = smem_u32(Bs);
    const int tid = threadIdx.x;

    auto loadA = [&](int c, int buf) {
        const __half* ag = Ag + c*HBK;
        const uint32_t dst = abase + buf*HASZ*2;
        #pragma unroll
        for (int it = 0; it < 2; it++) {
            int idx = tid + GTHR*it;
            int m = idx >> 3, k8 = idx & 7;
            cp16(dst + (m*HST + k8*8)*2, ag + (size_t)m*GD + k8*8);
        }
    };
    auto loadB = [&](int c, int buf) {
        const __half* bg = Bg + c*HBK;
        const uint32_t dst = bbase + buf*HBSZ*2;
        #pragma unroll
        for (int it = 0; it < 2; it++) {
            int idx = tid + GTHR*it;
            int n = idx >> 3, k8 = idx & 7;
            cp16(dst + (n*HST + k8*8)*2, bg + (size_t)n*GD + k8*8);
        }
    };

    loadA(0, 0); loadB(0, 0); cp_commit();
    loadA(1, 1); loadB(1, 1); cp_commit();

    const int wid = tid >> 5, lane = tid & 31;
    const int wm = wid & 3, wn = wid >> 2;   // 4 x 4 warp grid

    const int a_lrow = (lane & 7) + ((lane >> 3) & 1) * 8;
    const int a_lk   = (lane >> 4) * 8;
    const uint32_t a_lane = abase + ((wm*32 + a_lrow)*HST + a_lk) * 2;
    const int b_ln  = (lane & 7) + (lane >> 4) * 8;
    const int b_lk  = ((lane >> 3) & 1) * 8;
    const uint32_t b_lane = bbase + ((wn*32 + b_ln)*HST + b_lk) * 2;

    #pragma unroll
    for (int i = 0; i < 2; i++)
        #pragma unroll
        for (int j = 0; j < 4; j++)
            #pragma unroll
            for (int k = 0; k < 4; k++) G.a[i][j][k] = 0.f;

    int buf = 0, lbuf = 2;
    for (int c = 0; c < NCH; c++) {
        if (c + 1 < NCH) cp_wait1(); else cp_wait0();
        __syncthreads();
        if (c + 2 < NCH) {
            loadA(c+2, lbuf);
            loadB(c+2, lbuf);
            cp_commit();
        }

        const uint32_t ab = a_lane + buf*(HASZ*2);
        const uint32_t bb = b_lane + buf*(HBSZ*2);

        #pragma unroll
        for (int s = 0; s < 4; s++) {
            uint32_t a[2][4], b[4][2];
            ldsm_x4(a[0][0], a[0][1], a[0][2], a[0][3], ab + s*32);
            ldsm_x4(a[1][0], a[1][1], a[1][2], a[1][3], ab + 16*HST*2 + s*32);
            ldsm_x4(b[0][0], b[0][1], b[1][0], b[1][1], bb + s*32);
            ldsm_x4(b[2][0], b[2][1], b[3][0], b[3][1], bb + 16*HST*2 + s*32);
            #pragma unroll
            for (int mt = 0; mt < 2; mt++)
                #pragma unroll
                for (int nt = 0; nt < 4; nt++)
                    mma_f16(G.a[mt][nt], a[mt], b[nt][0], b[nt][1]);
        }

        buf  = (buf  == NSTAGE-1) ? 0 : buf + 1;
        lbuf = (lbuf == NSTAGE-1) ? 0 : lbuf + 1;
    }
}

// Fused QKV GEMM (by0 = M-tile offset for batch-half split).
__global__ void __launch_bounds__(GTHR, 2)
mma_gemm_qkv(const __half* __restrict__ A, const __half* __restrict__ BT,
             const float* __restrict__ bq, const float* __restrict__ bk,
             const float* __restrict__ bv,
             __half* __restrict__ Cq, __half* __restrict__ Ck, __half* __restrict__ Cvt,
             int by0)
{
    extern __shared__ __half smh[];
    const int bx = blockIdx.x, by = blockIdx.y + by0;
    const int mat = bx / 6;                  // 0=Q 1=K 2=V
    const float* bias = (mat == 0) ? bq : (mat == 1) ? bk : bv;
    const int bxm = bx - mat*6;
    const float oscale = (mat == 0) ? 0.125f : 1.f;

    GemmAcc G;
    gemm_mainloop(A + (size_t)(by*BM)*GD, BT + (size_t)(bx*BN)*GD,
                  smh, smh + NSTAGE*HASZ, G);

    const int tid = threadIdx.x, wid = tid >> 5, lane = tid & 31;
    const int wm = wid & 3, wn = wid >> 2;
    const int lr = lane >> 2, lq = lane & 3;

    #pragma unroll
    for (int mt = 0; mt < 2; mt++) {
        #pragma unroll
        for (int h8 = 0; h8 < 2; h8++) {
            const int row = by*BM + wm*32 + mt*16 + h8*8 + lr;
            const int bb = row / GN, nn = row % GN;
            #pragma unroll
            for (int nt = 0; nt < 4; nt++) {
                const int col = bxm*BN + wn*32 + nt*8 + 2*lq;
                float vx = (G.a[mt][nt][h8*2+0] + bias[col]) * oscale;
                float vy = (G.a[mt][nt][h8*2+1] + bias[col+1]) * oscale;
                const int h = col >> 6, hd = col & 63;
                if (mat == 2) {
                    __half* vt = Cvt + (((size_t)bb*GH + h)*GHD)*GN;
                    vt[(size_t)hd*GN + nn]     = __float2half(vx);
                    vt[(size_t)(hd+1)*GN + nn] = __float2half(vy);
                } else {
                    __half* C = (mat == 0) ? Cq : Ck;
                    uint32_t bits = h2_bits(vx, vy);
                    *(uint32_t*)(C + (((size_t)bb*GH + h)*GN + nn)*GHD + hd) = bits;
                }
            }
        }
    }
}

// Output GEMM: fp32 output + bias (by0 = M-tile offset).
__global__ void __launch_bounds__(GTHR, 2)
mma_gemm_out(const __half* __restrict__ A, const __half* __restrict__ BT,
             const float* __restrict__ bias, float* __restrict__ C, int by0)
{
    extern __shared__ __half smh[];
    const int bx = blockIdx.x, by = blockIdx.y + by0;

    GemmAcc G;
    gemm_mainloop(A + (size_t)(by*BM)*GD, BT + (size_t)(bx*BN)*GD,
                  smh, smh + NSTAGE*HASZ, G);

    const int tid = threadIdx.x, wid = tid >> 5, lane = tid & 31;
    const int wm = wid & 3, wn = wid >> 2;
    const int lr = lane >> 2, lq = lane & 3;

    #pragma unroll
    for (int mt = 0; mt < 2; mt++) {
        #pragma unroll
        for (int h8 = 0; h8 < 2; h8++) {
            const int row = by*BM + wm*32 + mt*16 + h8*8 + lr;
            #pragma unroll
            for (int nt = 0; nt < 4; nt++) {
                const int col = bx*BN + wn*32 + nt*8 + 2*lq;
                float2 v;
                v.x = G.a[mt][nt][h8*2+0] + bias[col];
                v.y = G.a[mt][nt][h8*2+1] + bias[col+1];
                *(float2*)(C + (size_t)row*GD + col) = v;
            }
        }
    }
}

// ============ Flash-mma attention (round-13 body, + block offset) ===========
#define AKST 72
#define AVST 216
#define ATT_SMEM (200*AKST*2 + 64*AVST*2 + 128*4)   // 57216 B

__global__ void __launch_bounds__(256, 3)
attn_flash(const __half* __restrict__ Qh, const __half* __restrict__ Kh,
           const __half* __restrict__ Vth, const float* __restrict__ Wsig,
           const float* __restrict__ bsigp, const float* __restrict__ tempp,
           __half* __restrict__ CTX, int blkoff)
{
    extern __shared__ __half smh[];
    __half* Ks = smh;                       // [200][72]
    __half* Vt = smh + 200*AKST;            // [64][216]
    float* invden = (float*)(smh + 200*AKST + 64*AVST);  // [128]

    const int bhx = blockIdx.x + blkoff;
    const int bh = bhx >> 1, chunk = bhx & 1;
    const __half* Qg  = Qh  + (size_t)bh * GN * GHD;
    const __half* Kg  = Kh  + (size_t)bh * GN * GHD;
    const __half* Vtg = Vth + (size_t)bh * GHD * GN;

    const int tid = threadIdx.x;

    for (int idx = tid; idx < GN*32; idx += 256) {
        int j = idx >> 5, dp = idx & 31;
        *(uint32_t*)&Ks[j*AKST + 2*dp] = *(const uint32_t*)&Kg[j*GHD + 2*dp];
    }
    for (int idx = tid; idx < GHD*98; idx += 256) {
        int d = idx / 98, jp = idx - d*98;
        *(uint32_t*)&Vt[d*AVST + 2*jp] = *(const uint32_t*)&Vtg[d*GN + 2*jp];
    }
    for (int idx = tid; idx < GHD*10; idx += 256) {
        int d = idx / 10, c = idx - d*10;
        *(uint32_t*)&Vt[d*AVST + GN + 2*c] = 0u;
    }
    if (tid < 128) {
        int r = chunk*128 + tid;
        if (r > GN-1) r = GN-1;
        const __half* qr = Qg + r*GHD;
        float acc = 0.f;
        #pragma unroll 8
        for (int dp = 0; dp < 32; dp++) {
            float2 q = __half22float2(*(const __half2*)&qr[2*dp]);
            float2 w = *(const float2*)&Wsig[2*dp];
            acc += q.x*w.x + q.y*w.y;
        }
        float x = acc*8.f + bsigp[0];
        float sp = (x > 20.f) ? x : log1pf(expf(x));
        float sg = (sp + 1e-3f) * tempp[0];
        invden[tid] = -1.f / (2.f*sg*sg);
    }
    __syncthreads();

    const int w = tid >> 5, lane = tid & 31;
    const int m0 = chunk*128 + w*16;
    if (m0 >= GN) return;    // warp-uniform; no further CTA syncs

    const int lr = lane >> 2, lq = lane & 3;
    const int row_lo = m0 + lr, row_hi = row_lo + 8;
    const int rlo = (row_lo > GN-1) ? GN-1 : row_lo;
    const int rhi = (row_hi > GN-1) ? GN-1 : row_hi;
    const float ivd_lo = invden[w*16 + lr];
    const float ivd_hi = invden[w*16 + lr + 8];
    const int iy_lo = (rlo*2341) >> 15, ix_lo = rlo - GSIDE*iy_lo;
    const int iy_hi = (rhi*2341) >> 15, ix_hi = rhi - GSIDE*iy_hi;

    const int lm_row = ((lane >> 4) & 1) * 8 + (lane & 7);
    const int lm_kof = ((lane >> 3) & 1) * 8;
    const uint32_t k_lane = smem_u32(Ks) + (lm_row*AKST + lm_kof) * 2;
    const uint32_t v_lane = smem_u32(Vt) + (lm_row*AVST + lm_kof) * 2;

    uint32_t qa[4][4];
    {
        const __half* qlo = Qg + rlo*GHD + 2*lq;
        const __half* qhi = Qg + rhi*GHD + 2*lq;
        #pragma unroll
        for (int ks = 0; ks < 4; ks++) {
            qa[ks][0] = *(const uint32_t*)&qlo[16*ks];
            qa[ks][1] = *(const uint32_t*)&qhi[16*ks];
            qa[ks][2] = *(const uint32_t*)&qlo[16*ks + 8];
            qa[ks][3] = *(const uint32_t*)&qhi[16*ks + 8];
        }
    }

    float ctx[8][4];
    #pragma unroll
    for (int nt = 0; nt < 8; nt++)
        #pragma unroll
        for (int c = 0; c < 4; c++) ctx[nt][c] = 0.f;
    float l_lo = 0.f, l_hi = 0.f;

    #pragma unroll 1
    for (int pr = 0; pr < 13; pr++) {
        uint32_t kb[4][4];
        const uint32_t kpr = k_lane + (pr*16*AKST)*2;
        #pragma unroll
        for (int ks = 0; ks < 4; ks++)
            ldsm_x4(kb[ks][0], kb[ks][1], kb[ks][2], kb[ks][3], kpr + ks*32);

        float sa[4] = {0.f,0.f,0.f,0.f}, sb[4] = {0.f,0.f,0.f,0.f};
        #pragma unroll
        for (int ks = 0; ks < 4; ks++) {
            mma_f16(sa, qa[ks], kb[ks][0], kb[ks][1]);
            mma_f16(sb, qa[ks], kb[ks][2], kb[ks][3]);
        }

        const int j0 = pr*16 + 2*lq;
        float p[8];
        #pragma unroll
        for (int t = 0; t < 4; t++) {
            const int j = j0 + (t & 1) + ((t & 2) << 2);   // j0,j0+1,j0+8,j0+9
            const float s = (t & 2) ? sb[t & 1 ? 1 : 0] : sa[t & 1];
            const float s_hi = (t & 2) ? sb[(t & 1) + 2] : sa[(t & 1) + 2];
            if (j < GN) {
                const int jy = (j*2341) >> 15, jx = j - GSIDE*jy;
                const int dyl = iy_lo - jy, dxl = ix_lo - jx;
                const int dyh = iy_hi - jy, dxh = ix_hi - jx;
                const float mlo = __expf((float)(dyl*dyl + dxl*dxl) * ivd_lo);
                const float mhi = __expf((float)(dyh*dyh + dxh*dxh) * ivd_hi);
                p[t*2]   = __expf(mlo * s);
                p[t*2+1] = __expf(mhi * s_hi);
            } else {
                p[t*2] = 0.f;
                p[t*2+1] = 0.f;
            }
        }
        l_lo += (p[0] + p[2]) + (p[4] + p[6]);
        l_hi += (p[1] + p[3]) + (p[5] + p[7]);

        uint32_t pa[4];
        pa[0] = h2_bits(p[0], p[2]);
        pa[1] = h2_bits(p[1], p[3]);
        pa[2] = h2_bits(p[4], p[6]);
        pa[3] = h2_bits(p[5], p[7]);

        const uint32_t vpr = v_lane + (pr*16)*2;
        #pragma unroll
        for (int dg = 0; dg < 4; dg++) {
            uint32_t vb0, vb1, vb2, vb3;
            ldsm_x4(vb0, vb1, vb2, vb3, vpr + dg*(16*AVST)*2);
            mma_f16(ctx[2*dg],     pa, vb0, vb1);
            mma_f16(ctx[2*dg + 1], pa, vb2, vb3);
        }
    }

    l_lo += __shfl_xor_sync(0xffffffffu, l_lo, 1);
    l_lo += __shfl_xor_sync(0xffffffffu, l_lo, 2);
    l_hi += __shfl_xor_sync(0xffffffffu, l_hi, 1);
    l_hi += __shfl_xor_sync(0xffffffffu, l_hi, 2);
    const float il_lo = 1.f / l_lo, il_hi = 1.f / l_hi;

    const int b = bh / GH, h = bh % GH;
    __half* out_lo = CTX + ((size_t)(b*GN + row_lo))*GD + h*GHD + 2*lq;
    __half* out_hi = CTX + ((size_t)(b*GN + row_hi))*GD + h*GHD + 2*lq;
    #pragma unroll
    for (int nt = 0; nt < 8; nt++) {
        if (row_lo < GN)
            *(uint32_t*)&out_lo[nt*8] = h2_bits(ctx[nt][0]*il_lo, ctx[nt][1]*il_lo);
        if (row_hi < GN)
            *(uint32_t*)&out_hi[nt*8] = h2_bits(ctx[nt][2]*il_hi, ctx[nt][3]*il_hi);
    }
}

// ---------------- launch: two batch-half chains on two streams --------------
static cudaStream_t g_s1 = nullptr;
static cudaEvent_t  g_ef = nullptr;   // fork
static cudaEvent_t  g_ej = nullptr;   // join

extern "C" void kernel_launch(void* const* d_in, const int* in_sizes, int n_in,
                              void* d_out, int out_size)
{
    const float* hs   = (const float*)d_in[0];
    const float* temp = (const float*)d_in[1];
    const float* Wq   = (const float*)d_in[2];
    const float* bq   = (const float*)d_in[3];
    const float* Wk   = (const float*)d_in[4];
    const float* bk   = (const float*)d_in[5];
    const float* Wv   = (const float*)d_in[6];
    const float* bv   = (const float*)d_in[7];
    const float* Wo   = (const float*)d_in[8];
    const float* bo   = (const float*)d_in[9];
    const float* Wsig = (const float*)d_in[10];
    const float* bsig = (const float*)d_in[11];
    float* out = (float*)d_out;

    __half *gq, *gk, *gvt, *ghs, *gwt, *gctx;
    cudaGetSymbolAddress((void**)&gq,   g_q_h);
    cudaGetSymbolAddress((void**)&gk,   g_k_h);
    cudaGetSymbolAddress((void**)&gvt,  g_vt_h);
    cudaGetSymbolAddress((void**)&ghs,  g_hs_h);
    cudaGetSymbolAddress((void**)&gwt,  g_wt_h);
    cudaGetSymbolAddress((void**)&gctx, g_ctx_h);

    cudaFuncSetAttribute(attn_flash,
                         cudaFuncAttributeMaxDynamicSharedMemorySize, ATT_SMEM);
    cudaFuncSetAttribute(mma_gemm_qkv,
                         cudaFuncAttributeMaxDynamicSharedMemorySize, GEMM_SMEM);
    cudaFuncSetAttribute(mma_gemm_out,
                         cudaFuncAttributeMaxDynamicSharedMemorySize, GEMM_SMEM);

    if (!g_s1) {
        cudaStreamCreateWithFlags(&g_s1, cudaStreamNonBlocking);
        cudaEventCreateWithFlags(&g_ef, cudaEventDisableTiming);
        cudaEventCreateWithFlags(&g_ej, cudaEventDisableTiming);
    }

    __half* wto = gwt + 3ull*GD*GD;

    // shared pre-passes on the capture stream
    const int nhs4 = GM*GD/4;
    conv_f2h<<<(nhs4 + 255)/256, 256>>>(hs, ghs, nhs4);
    dim3 tb(32, 8), tg(GD/32, GD/32, 4);
    transpose_f2h4<<<tg, tb>>>(Wq, Wk, Wv, Wo, gwt);

    // fork side stream
    cudaEventRecord(g_ef, 0);
    cudaStreamWaitEvent(g_s1, g_ef, 0);

    // chain A (batches 0-31): M-tiles 0-48, heads 0-383 (blk 0-767)
    dim3 gqkvh(3*GD/BN, 49);   // (18, 49)
    dim3 gouth(GD/BN, 49);     // (6, 49)
    mma_gemm_qkv<<<gqkvh, GTHR, GEMM_SMEM>>>(ghs, gwt, bq, bk, bv, gq, gk, gvt, 0);
    attn_flash<<<GB*GH, 256, ATT_SMEM>>>(gq, gk, gvt, Wsig, bsig, temp, gctx, 0);
    mma_gemm_out<<<gouth, GTHR, GEMM_SMEM>>>(gctx, wto, bo, out, 0);

    // chain B (batches 32-63): M-tiles 49-97, heads 384-767 (blk 768-1535)
    mma_gemm_qkv<<<gqkvh, GTHR, GEMM_SMEM, g_s1>>>(ghs, gwt, bq, bk, bv, gq, gk, gvt, 49);
    attn_flash<<<GB*GH, 256, ATT_SMEM, g_s1>>>(gq, gk, gvt, Wsig, bsig, temp, gctx, GB*GH);
    mma_gemm_out<<<gouth, GTHR, GEMM_SMEM, g_s1>>>(gctx, wto, bo, out, 49);

    // join
    cudaEventRecord(g_ej, g_s1);
    cudaStreamWaitEvent(0, g_ej, 0);
}